// round 12
// baseline (speedup 1.0000x reference)
#include <cuda_runtime.h>
#include <cuda_bf16.h>
#include <math.h>
#include <stdint.h>

// Problem constants
#define BATCH   2
#define NPTS    2048
#define HEADS   8
#define DHEAD   64
#define KNB     32
#define DIMF    512
#define INNER   512          // HEADS*DHEAD
#define QKVN    1536         // 3*INNER
#define ROWS    (BATCH*NPTS) // 4096
#define FEAT_OUT (ROWS*DIMF) // 2097152
#define KDIM    512          // contraction dim for BOTH GEMMs (DIMF == INNER)

#define U64MAX 0xFFFFFFFFFFFFFFFFULL
#define BND_MAX 256

// Scratch (device globals: allocation-free per harness rules)
__device__ float g_qkv[ROWS * QKVN];   // 25.2 MB
__device__ float g_att[ROWS * INNER];  // 8.4 MB

// ---------------------------------------------------------------------------
// TF32 tensor-core GEMM with register-prefetch double buffering.
// K is compile-time (KDIM=512) -> fully unrollable, constant addressing.
// ---------------------------------------------------------------------------
__device__ __forceinline__ uint32_t f2tf32(float x) {
    uint32_t r;
    asm("cvt.rna.tf32.f32 %0, %1;" : "=r"(r) : "f"(x));
    return r;
}

__global__ __launch_bounds__(256) void tf32_gemm_kernel(
    const float* __restrict__ A, const float* __restrict__ Bm,
    float* __restrict__ C, int M, int N,
    const float* __restrict__ bias)
{
    constexpr int BM = 128, BN = 128, BK = 32;
    constexpr int AP = BK + 4;   // 36
    constexpr int BP = BN + 8;   // 136
    __shared__ uint32_t As[BM * AP];
    __shared__ uint32_t Bs[BK * BP];

    const int tid = threadIdx.x;
    const int lane = tid & 31;
    const int wid = tid >> 5;
    const int wm = wid & 1;
    const int wn = wid >> 1;
    const int row0 = blockIdx.y * BM;
    const int col0 = blockIdx.x * BN;

    const int g  = lane >> 2;
    const int tg = lane & 3;

    float acc[4][4][4];
#pragma unroll
    for (int i = 0; i < 4; i++)
#pragma unroll
        for (int j = 0; j < 4; j++)
#pragma unroll
            for (int r = 0; r < 4; r++) acc[i][j][r] = 0.f;

    const int ar = tid >> 3;
    const int ac = (tid & 7) * 4;
    const int br = tid >> 5;
    const int bc = (tid & 31) * 4;

    float4 pa[4], pb[4];
#pragma unroll
    for (int p = 0; p < 4; p++) {
        pa[p] = *(const float4*)&A[(long)(row0 + ar + p * 32) * KDIM + ac];
        pb[p] = *(const float4*)&Bm[(long)(br + p * 8) * N + col0 + bc];
    }

#pragma unroll 1
    for (int kk = 0; kk < KDIM; kk += BK) {
#pragma unroll
        for (int p = 0; p < 4; p++) {
            uint32_t* as = &As[(ar + p * 32) * AP + ac];
            as[0] = f2tf32(pa[p].x); as[1] = f2tf32(pa[p].y);
            as[2] = f2tf32(pa[p].z); as[3] = f2tf32(pa[p].w);
            uint32_t* bs = &Bs[(br + p * 8) * BP + bc];
            bs[0] = f2tf32(pb[p].x); bs[1] = f2tf32(pb[p].y);
            bs[2] = f2tf32(pb[p].z); bs[3] = f2tf32(pb[p].w);
        }
        __syncthreads();

        if (kk + BK < KDIM) {
#pragma unroll
            for (int p = 0; p < 4; p++) {
                pa[p] = *(const float4*)&A[(long)(row0 + ar + p * 32) * KDIM + kk + BK + ac];
                pb[p] = *(const float4*)&Bm[(long)(kk + BK + br + p * 8) * N + col0 + bc];
            }
        }

#pragma unroll
        for (int ks = 0; ks < 4; ks++) {
            const int k0 = ks * 8;
            uint32_t a[4][4], b[4][2];
#pragma unroll
            for (int mi = 0; mi < 4; mi++) {
                const int r = wm * 64 + mi * 16 + g;
                a[mi][0] = As[r * AP + k0 + tg];
                a[mi][1] = As[(r + 8) * AP + k0 + tg];
                a[mi][2] = As[r * AP + k0 + tg + 4];
                a[mi][3] = As[(r + 8) * AP + k0 + tg + 4];
            }
#pragma unroll
            for (int nj = 0; nj < 4; nj++) {
                const int c = wn * 32 + nj * 8 + g;
                b[nj][0] = Bs[(k0 + tg) * BP + c];
                b[nj][1] = Bs[(k0 + tg + 4) * BP + c];
            }
#pragma unroll
            for (int mi = 0; mi < 4; mi++)
#pragma unroll
                for (int nj = 0; nj < 4; nj++) {
                    asm volatile(
                        "mma.sync.aligned.m16n8k8.row.col.f32.tf32.tf32.f32 "
                        "{%0,%1,%2,%3}, {%4,%5,%6,%7}, {%8,%9}, {%0,%1,%2,%3};"
                        : "+f"(acc[mi][nj][0]), "+f"(acc[mi][nj][1]),
                          "+f"(acc[mi][nj][2]), "+f"(acc[mi][nj][3])
                        : "r"(a[mi][0]), "r"(a[mi][1]), "r"(a[mi][2]), "r"(a[mi][3]),
                          "r"(b[nj][0]), "r"(b[nj][1]));
                }
        }
        __syncthreads();
    }

#pragma unroll
    for (int mi = 0; mi < 4; mi++) {
        const int r = row0 + wm * 64 + mi * 16 + g;
#pragma unroll
        for (int nj = 0; nj < 4; nj++) {
            const int c = col0 + wn * 32 + nj * 8 + 2 * tg;
            float b0 = bias ? bias[c] : 0.f;
            float b1 = bias ? bias[c + 1] : 0.f;
            C[(long)r * N + c]           = acc[mi][nj][0] + b0;
            C[(long)r * N + c + 1]       = acc[mi][nj][1] + b1;
            C[(long)(r + 8) * N + c]     = acc[mi][nj][2] + b0;
            C[(long)(r + 8) * N + c + 1] = acc[mi][nj][3] + b1;
        }
    }
}

// ---------------------------------------------------------------------------
// Fused selection + attention kernel. Histogram (radix-threshold) top-32
// selection + float2 pair-based gather loops.
// __launch_bounds__(256, 3): cap regs so 3 CTAs/SM stay resident (24 warps)
// to cover the gather-phase L2 latency.
// ---------------------------------------------------------------------------
__global__ __launch_bounds__(256, 3) void sa_kernel(
    const float* __restrict__ coors,
    const float* __restrict__ wc1, const float* __restrict__ bc1,
    const float* __restrict__ wc2, const float* __restrict__ bc2,
    const float* __restrict__ wg,  const float* __restrict__ bg,
    const float* __restrict__ coors_scale,
    const float* __restrict__ coors_combine,
    float* __restrict__ out_coors)
{
    const int row = blockIdx.x;
    const int b = row >> 11;             // / NPTS
    const int i = row & (NPTS - 1);
    const int tid = threadIdx.x;
    const int lane = tid & 31;
    const int warp = tid >> 5;           // warp == head

    __shared__ int   s_hist[2048];       // 8KB  (bin = d2 bits >> 20)
    __shared__ int   s_chunk[256];       // 1KB
    __shared__ unsigned long long s_bnd[BND_MAX];  // 2KB
    __shared__ unsigned long long s_sel[KNB];
    __shared__ int   s_na, s_nb, s_T;
    __shared__ int   s_idx[KNB];
    __shared__ float s_dist[KNB];
    __shared__ float s_cos[KNB][32];
    __shared__ float s_sin[KNB][32];
    __shared__ float s_qk[HEADS][KNB];
    __shared__ float s_attn[HEADS][KNB];
    __shared__ float s_cw[KNB][HEADS];
    __shared__ float s_gate[KNB][HEADS];
    __shared__ float s_hid[KNB][16];
    __shared__ float s_ci[3];

    const float* cb = coors + (long)b * NPTS * 3;
    if (tid < 3) s_ci[tid] = cb[i * 3 + tid];
    for (int t = tid; t < 2048; t += 256) s_hist[t] = 0;
    if (tid == 0) { s_na = 0; s_nb = 0; }
    __syncthreads();
    const float cix = s_ci[0], ciy = s_ci[1], ciz = s_ci[2];

    // q preloads (rotary with zero freqs is identity)
    const int hb = warp * DHEAD;
    const long qbase = (long)row * QKVN + hb;
    const float2 qp = *(const float2*)&g_qkv[qbase + 2 * lane];  // q[2l], q[2l+1]
    const float qA = g_qkv[qbase + lane];                        // q[l]
    const float qB = g_qkv[qbase + lane + 32];                   // q[l+32]

    // ---- Selection step 1: d2 + histogram ----
    float d2v[8];
#pragma unroll
    for (int u = 0; u < 8; u++) {
        int j = u * 256 + tid;
        float dx = cix - cb[j * 3 + 0];
        float dy = ciy - cb[j * 3 + 1];
        float dz = ciz - cb[j * 3 + 2];
        float d2 = dx * dx + dy * dy + dz * dz;
        d2v[u] = d2;
        atomicAdd(&s_hist[__float_as_uint(d2) >> 20], 1);
    }
    __syncthreads();

    // ---- Step 2: find threshold bin T (smallest with cum >= 32) ----
    {
        int csum = 0;
#pragma unroll
        for (int t = 0; t < 8; t++) csum += s_hist[tid * 8 + t];
        s_chunk[tid] = csum;
    }
    __syncthreads();
    if (warp == 0) {
        int g = 0;
#pragma unroll
        for (int t = 0; t < 8; t++) g += s_chunk[lane * 8 + t];
        int cum = g;
#pragma unroll
        for (int off = 1; off < 32; off <<= 1) {
            int o = __shfl_up_sync(0xFFFFFFFFu, cum, off);
            if (lane >= off) cum += o;
        }
        unsigned ball = __ballot_sync(0xFFFFFFFFu, cum >= KNB);
        int firstl = __ffs(ball) - 1;
        if (lane == firstl) {
            int c = cum - g;   // exclusive cum before this lane's 8 chunks
            int T = -1;
            for (int t = 0; t < 8 && T < 0; t++) {
                int ch = lane * 8 + t;
                int cs = s_chunk[ch];
                if (c + cs >= KNB) {
                    for (int bd = 0; bd < 8; bd++) {
                        int bin = ch * 8 + bd;
                        int hv = s_hist[bin];
                        if (c + hv >= KNB) { T = bin; break; }
                        c += hv;
                    }
                } else c += cs;
            }
            s_T = T;
        }
    }
    __syncthreads();
    const int Tbin = s_T;

    // ---- Step 3: compaction ----
#pragma unroll
    for (int u = 0; u < 8; u++) {
        int j = u * 256 + tid;
        unsigned bits = __float_as_uint(d2v[u]);
        int key = (int)(bits >> 20);
        if (key < Tbin) {
            int pos = atomicAdd(&s_na, 1);
            s_sel[pos] = ((unsigned long long)bits << 32) | (unsigned)j;
        } else if (key == Tbin) {
            int pos = atomicAdd(&s_nb, 1);
            if (pos < BND_MAX)
                s_bnd[pos] = ((unsigned long long)bits << 32) | (unsigned)j;
        }
    }
    __syncthreads();

    // ---- Step 4: pick the remaining (32 - na) smallest from boundary bin ----
    if (warp == 0) {
        const int na = s_na;
        const int nb = min(s_nb, BND_MAX);
        const int krem = KNB - na;
        for (int r = 0; r < krem; r++) {
            unsigned long long m = U64MAX;
            for (int t = lane; t < nb; t += 32) m = min(m, s_bnd[t]);
#pragma unroll
            for (int off = 16; off; off >>= 1) {
                unsigned long long o = __shfl_xor_sync(0xFFFFFFFFu, m, off);
                m = min(m, o);
            }
            for (int t = lane; t < nb; t += 32)
                if (s_bnd[t] == m) s_bnd[t] = U64MAX;
            if (lane == 0) s_sel[na + r] = m;
            __syncwarp();
        }
    }
    __syncthreads();

    if (tid < KNB) {
        unsigned long long k = s_sel[tid];
        s_idx[tid]  = (int)(k & 0xFFFFFFFFu);
        s_dist[tid] = sqrtf(__uint_as_float((unsigned)(k >> 32)));
    }
    __syncthreads();

    // rotary cos/sin: freqs[m] = min(dist*100,5000) * 10000^(-2m/64)
    {
        const int m = tid & 31;
        const float invf = exp2f((float)m * -0.41524099657040455f);
#pragma unroll
        for (int idx = tid; idx < KNB * 32; idx += 256) {
            int r = idx >> 5;
            float t = fminf(s_dist[r] * 100.0f, 5000.0f);
            float s, c;
            __sincosf(t * invf, &s, &c);
            s_cos[r][m] = c;
            s_sin[r][m] = s;
        }
    }
    __syncthreads();

    // qk logits: lane l holds k pair (2l, 2l+1); zero rotate-half shuffles.
    const int si1 = lane >> 1;
    const int si2 = 16 + (lane >> 1);
#pragma unroll 4
    for (int r = 0; r < KNB; r++) {
        const long kb = (long)(b * NPTS + s_idx[r]) * QKVN + INNER + hb;
        float2 kv = *(const float2*)&g_qkv[kb + 2 * lane];
        float C  = s_cos[r][lane];
        float S1 = s_sin[r][si1];
        float S2 = s_sin[r][si2];
        float t = fmaf(qp.y, kv.y, qp.x * kv.x);
        float sum = C * t;
        sum = fmaf(S2, qB * kv.x, sum);
        sum = fmaf(-S1, qA * kv.y, sum);
#pragma unroll
        for (int off = 16; off; off >>= 1)
            sum += __shfl_down_sync(0xFFFFFFFFu, sum, off);
        if (lane == 0) s_qk[warp][r] = sum * 0.125f;
    }
    __syncthreads();

    // tiny MLPs, parallel over (neighbor j, head/slot s): tid = j*8 + s
    {
        const int j = tid >> 3;
        const int s = tid & 7;
        float in[HEADS];
#pragma unroll
        for (int h = 0; h < HEADS; h++) in[h] = s_qk[h][j];
#pragma unroll
        for (int t = 0; t < 2; t++) {
            const int m = 2 * s + t;
            float a = bc1[m];
#pragma unroll
            for (int h = 0; h < HEADS; h++) a += in[h] * wc1[h * 16 + m];
            float x3 = a * a * a;
            float tt = tanhf(0.7978845608028654f * (a + 0.044715f * x3));
            s_hid[j][m] = 0.5f * a * (1.0f + tt);
        }
        __syncwarp();
        float a = bc2[s];
#pragma unroll
        for (int m = 0; m < 16; m++) a += s_hid[j][m] * wc2[m * 8 + s];
        s_cw[j][s] = a;
        float gg = bg[s];
#pragma unroll
        for (int h = 0; h < HEADS; h++) gg += in[h] * wg[h * 8 + s];
        s_gate[j][s] = tanhf(gg);
    }
    __syncthreads();

    // softmaxes: warp h handles head h, lane j handles neighbor j
    {
        const int h = warp;
        float v = s_qk[h][lane];
        float mx = v;
#pragma unroll
        for (int off = 16; off; off >>= 1)
            mx = fmaxf(mx, __shfl_xor_sync(0xFFFFFFFFu, mx, off));
        float e = expf(v - mx);
        float ssum = e;
#pragma unroll
        for (int off = 16; off; off >>= 1)
            ssum += __shfl_xor_sync(0xFFFFFFFFu, ssum, off);
        s_attn[h][lane] = e / ssum;

        float w = s_cw[lane][h];
        float mx2 = w;
#pragma unroll
        for (int off = 16; off; off >>= 1)
            mx2 = fmaxf(mx2, __shfl_xor_sync(0xFFFFFFFFu, mx2, off));
        float e2 = expf(w - mx2);
        float ssum2 = e2;
#pragma unroll
        for (int off = 16; off; off >>= 1)
            ssum2 += __shfl_xor_sync(0xFFFFFFFFu, ssum2, off);
        s_cw[lane][h] = e2 / ssum2;
    }
    __syncthreads();

    // coordinates output: warp 0, lane j = neighbor j
    if (warp == 0 && out_coors) {
        float w = 0.f;
#pragma unroll
        for (int h = 0; h < HEADS; h++)
            w += s_cw[lane][h] * s_gate[lane][h] * coors_combine[h];
        const int jj = s_idx[lane];
        const float nrm = fmaxf(s_dist[lane], 1e-8f);
        const float cscale = coors_scale[0] * w / nrm;
        float vx = (cix - cb[jj * 3 + 0]) * cscale;
        float vy = (ciy - cb[jj * 3 + 1]) * cscale;
        float vz = (ciz - cb[jj * 3 + 2]) * cscale;
#pragma unroll
        for (int off = 16; off; off >>= 1) {
            vx += __shfl_xor_sync(0xFFFFFFFFu, vx, off);
            vy += __shfl_xor_sync(0xFFFFFFFFu, vy, off);
            vz += __shfl_xor_sync(0xFFFFFFFFu, vz, off);
        }
        if (lane == 0) {
            out_coors[(long)row * 3 + 0] = vx;
            out_coors[(long)row * 3 + 1] = vy;
            out_coors[(long)row * 3 + 2] = vz;
        }
    }

    // feature output: lane l accumulates dims (2l, 2l+1).
    const int sA = (2 * lane) & 31;
    const int sB = (2 * lane + 1) & 31;
    const bool lo = lane < 16;
    float acc1 = 0.f, acc2 = 0.f;
#pragma unroll 4
    for (int r = 0; r < KNB; r++) {
        const long vb = (long)(b * NPTS + s_idx[r]) * QKVN + 2 * INNER + hb;
        float2 vv = *(const float2*)&g_qkv[vb + 2 * lane];
        float ya = __shfl_sync(0xFFFFFFFFu, vv.y, sA);
        float xa = __shfl_sync(0xFFFFFFFFu, vv.x, sA);
        float yb = __shfl_sync(0xFFFFFFFFu, vv.y, sB);
        float xb = __shfl_sync(0xFFFFFFFFu, vv.x, sB);
        float rot0 = lo ? -ya : xa;
        float rot1 = lo ? -yb : xb;
        float C = s_cos[r][lane];
        float S = s_sin[r][lane];
        float a = s_attn[warp][r];
        float t0 = fmaf(rot0, S, vv.x * C);
        float t1 = fmaf(rot1, S, vv.y * C);
        acc1 = fmaf(a, t0, acc1);
        acc2 = fmaf(a, t1, acc2);
    }
    *(float2*)&g_att[(long)row * INNER + hb + 2 * lane] = make_float2(acc1, acc2);
}

// ---------------------------------------------------------------------------
extern "C" void kernel_launch(void* const* d_in, const int* in_sizes, int n_in,
                              void* d_out, int out_size)
{
    const float* feats         = (const float*)d_in[0];
    const float* coors         = (const float*)d_in[1];
    const float* w_qkv         = (const float*)d_in[2];
    const float* w_out         = (const float*)d_in[3];
    const float* b_out         = (const float*)d_in[4];
    const float* wc1           = (const float*)d_in[5];
    const float* bc1           = (const float*)d_in[6];
    const float* wc2           = (const float*)d_in[7];
    const float* bc2           = (const float*)d_in[8];
    const float* wg            = (const float*)d_in[9];
    const float* bg            = (const float*)d_in[10];
    const float* coors_scale   = (const float*)d_in[11];
    const float* coors_combine = (const float*)d_in[12];

    float* out = (float*)d_out;
    float* out_coors = (out_size >= FEAT_OUT + ROWS * 3) ? out + FEAT_OUT : nullptr;

    float* qkv_ptr = nullptr;
    float* att_ptr = nullptr;
    cudaGetSymbolAddress((void**)&qkv_ptr, g_qkv);
    cudaGetSymbolAddress((void**)&att_ptr, g_att);

    // 1) qkv = feats @ w_qkv  (TF32 tensor cores)
    {
        dim3 grid(QKVN / 128, ROWS / 128);
        tf32_gemm_kernel<<<grid, 256>>>(feats, w_qkv, qkv_ptr, ROWS, QKVN, nullptr);
    }
    // 2) fused neighbor selection (histogram top-k) + attention
    sa_kernel<<<ROWS, 256>>>(coors, wc1, bc1, wc2, bc2, wg, bg,
                             coors_scale, coors_combine, out_coors);
    // 3) out = att @ w_out + b_out  (TF32 tensor cores)
    {
        dim3 grid(DIMF / 128, ROWS / 128);
        tf32_gemm_kernel<<<grid, 256>>>(att_ptr, w_out, out, ROWS, DIMF, b_out);
    }
}

// round 13
// speedup vs baseline: 1.2481x; 1.2481x over previous
#include <cuda_runtime.h>
#include <cuda_bf16.h>
#include <math.h>
#include <stdint.h>

// Problem constants
#define BATCH   2
#define NPTS    2048
#define HEADS   8
#define DHEAD   64
#define KNB     32
#define DIMF    512
#define INNER   512          // HEADS*DHEAD
#define QKVN    1536         // 3*INNER
#define ROWS    (BATCH*NPTS) // 4096
#define FEAT_OUT (ROWS*DIMF) // 2097152

#define U64MAX 0xFFFFFFFFFFFFFFFFULL
#define BND_MAX 256

// Scratch (device globals: allocation-free per harness rules)
__device__ float g_qkv[ROWS * QKVN];   // 25.2 MB
__device__ float g_att[ROWS * INNER];  // 8.4 MB

// ---------------------------------------------------------------------------
// TF32 tensor-core GEMM with register-prefetch double buffering (R11 version).
// ---------------------------------------------------------------------------
__device__ __forceinline__ uint32_t f2tf32(float x) {
    uint32_t r;
    asm("cvt.rna.tf32.f32 %0, %1;" : "=r"(r) : "f"(x));
    return r;
}

__global__ __launch_bounds__(256) void tf32_gemm_kernel(
    const float* __restrict__ A, const float* __restrict__ Bm,
    float* __restrict__ C, int M, int N, int K,
    const float* __restrict__ bias)
{
    constexpr int BM = 128, BN = 128, BK = 32;
    constexpr int AP = BK + 4;   // 36
    constexpr int BP = BN + 8;   // 136
    __shared__ uint32_t As[BM * AP];
    __shared__ uint32_t Bs[BK * BP];

    const int tid = threadIdx.x;
    const int lane = tid & 31;
    const int wid = tid >> 5;
    const int wm = wid & 1;
    const int wn = wid >> 1;
    const int row0 = blockIdx.y * BM;
    const int col0 = blockIdx.x * BN;

    const int g  = lane >> 2;
    const int tg = lane & 3;

    float acc[4][4][4];
#pragma unroll
    for (int i = 0; i < 4; i++)
#pragma unroll
        for (int j = 0; j < 4; j++)
#pragma unroll
            for (int r = 0; r < 4; r++) acc[i][j][r] = 0.f;

    const int ar = tid >> 3;
    const int ac = (tid & 7) * 4;
    const int br = tid >> 5;
    const int bc = (tid & 31) * 4;

    float4 pa[4], pb[4];
#pragma unroll
    for (int p = 0; p < 4; p++) {
        pa[p] = *(const float4*)&A[(long)(row0 + ar + p * 32) * K + ac];
        pb[p] = *(const float4*)&Bm[(long)(br + p * 8) * N + col0 + bc];
    }

    for (int kk = 0; kk < K; kk += BK) {
#pragma unroll
        for (int p = 0; p < 4; p++) {
            uint32_t* as = &As[(ar + p * 32) * AP + ac];
            as[0] = f2tf32(pa[p].x); as[1] = f2tf32(pa[p].y);
            as[2] = f2tf32(pa[p].z); as[3] = f2tf32(pa[p].w);
            uint32_t* bs = &Bs[(br + p * 8) * BP + bc];
            bs[0] = f2tf32(pb[p].x); bs[1] = f2tf32(pb[p].y);
            bs[2] = f2tf32(pb[p].z); bs[3] = f2tf32(pb[p].w);
        }
        __syncthreads();

        if (kk + BK < K) {
#pragma unroll
            for (int p = 0; p < 4; p++) {
                pa[p] = *(const float4*)&A[(long)(row0 + ar + p * 32) * K + kk + BK + ac];
                pb[p] = *(const float4*)&Bm[(long)(kk + BK + br + p * 8) * N + col0 + bc];
            }
        }

#pragma unroll
        for (int ks = 0; ks < 4; ks++) {
            const int k0 = ks * 8;
            uint32_t a[4][4], b[4][2];
#pragma unroll
            for (int mi = 0; mi < 4; mi++) {
                const int r = wm * 64 + mi * 16 + g;
                a[mi][0] = As[r * AP + k0 + tg];
                a[mi][1] = As[(r + 8) * AP + k0 + tg];
                a[mi][2] = As[r * AP + k0 + tg + 4];
                a[mi][3] = As[(r + 8) * AP + k0 + tg + 4];
            }
#pragma unroll
            for (int nj = 0; nj < 4; nj++) {
                const int c = wn * 32 + nj * 8 + g;
                b[nj][0] = Bs[(k0 + tg) * BP + c];
                b[nj][1] = Bs[(k0 + tg + 4) * BP + c];
            }
#pragma unroll
            for (int mi = 0; mi < 4; mi++)
#pragma unroll
                for (int nj = 0; nj < 4; nj++) {
                    asm volatile(
                        "mma.sync.aligned.m16n8k8.row.col.f32.tf32.tf32.f32 "
                        "{%0,%1,%2,%3}, {%4,%5,%6,%7}, {%8,%9}, {%0,%1,%2,%3};"
                        : "+f"(acc[mi][nj][0]), "+f"(acc[mi][nj][1]),
                          "+f"(acc[mi][nj][2]), "+f"(acc[mi][nj][3])
                        : "r"(a[mi][0]), "r"(a[mi][1]), "r"(a[mi][2]), "r"(a[mi][3]),
                          "r"(b[nj][0]), "r"(b[nj][1]));
                }
        }
        __syncthreads();
    }

#pragma unroll
    for (int mi = 0; mi < 4; mi++) {
        const int r = row0 + wm * 64 + mi * 16 + g;
#pragma unroll
        for (int nj = 0; nj < 4; nj++) {
            const int c = col0 + wn * 32 + nj * 8 + 2 * tg;
            float b0 = bias ? bias[c] : 0.f;
            float b1 = bias ? bias[c + 1] : 0.f;
            C[(long)r * N + c]           = acc[mi][nj][0] + b0;
            C[(long)r * N + c + 1]       = acc[mi][nj][1] + b1;
            C[(long)(r + 8) * N + c]     = acc[mi][nj][2] + b0;
            C[(long)(r + 8) * N + c + 1] = acc[mi][nj][3] + b1;
        }
    }
}

// ---------------------------------------------------------------------------
// Fused selection + attention kernel (R11 structure; q preloads moved after
// selection to shorten live ranges; clamped compaction writes).
// ---------------------------------------------------------------------------
__global__ __launch_bounds__(256) void sa_kernel(
    const float* __restrict__ coors,
    const float* __restrict__ wc1, const float* __restrict__ bc1,
    const float* __restrict__ wc2, const float* __restrict__ bc2,
    const float* __restrict__ wg,  const float* __restrict__ bg,
    const float* __restrict__ coors_scale,
    const float* __restrict__ coors_combine,
    float* __restrict__ out_coors)
{
    const int row = blockIdx.x;
    const int b = row >> 11;             // / NPTS
    const int i = row & (NPTS - 1);
    const int tid = threadIdx.x;
    const int lane = tid & 31;
    const int warp = tid >> 5;           // warp == head

    __shared__ int   s_hist[2048];       // 8KB  (bin = d2 bits >> 20)
    __shared__ int   s_chunk[256];       // 1KB
    __shared__ unsigned long long s_bnd[BND_MAX];  // 2KB
    __shared__ unsigned long long s_sel[KNB];
    __shared__ int   s_na, s_nb, s_T;
    __shared__ int   s_idx[KNB];
    __shared__ float s_dist[KNB];
    __shared__ float s_cos[KNB][32];
    __shared__ float s_sin[KNB][32];
    __shared__ float s_qk[HEADS][KNB];
    __shared__ float s_attn[HEADS][KNB];
    __shared__ float s_cw[KNB][HEADS];
    __shared__ float s_gate[KNB][HEADS];
    __shared__ float s_hid[KNB][16];
    __shared__ float s_ci[3];

    const float* cb = coors + (long)b * NPTS * 3;
    if (tid < 3) s_ci[tid] = cb[i * 3 + tid];
    for (int t = tid; t < 2048; t += 256) s_hist[t] = 0;
    if (tid == 0) { s_na = 0; s_nb = 0; }
    __syncthreads();
    const float cix = s_ci[0], ciy = s_ci[1], ciz = s_ci[2];

    // ---- Selection step 1: d2 + histogram ----
    float d2v[8];
#pragma unroll
    for (int u = 0; u < 8; u++) {
        int j = u * 256 + tid;
        float dx = cix - cb[j * 3 + 0];
        float dy = ciy - cb[j * 3 + 1];
        float dz = ciz - cb[j * 3 + 2];
        float d2 = dx * dx + dy * dy + dz * dz;
        d2v[u] = d2;
        atomicAdd(&s_hist[__float_as_uint(d2) >> 20], 1);
    }
    __syncthreads();

    // ---- Step 2: find threshold bin T (smallest with cum >= 32) ----
    {
        int csum = 0;
#pragma unroll
        for (int t = 0; t < 8; t++) csum += s_hist[tid * 8 + t];
        s_chunk[tid] = csum;
    }
    __syncthreads();
    if (warp == 0) {
        int g = 0;
#pragma unroll
        for (int t = 0; t < 8; t++) g += s_chunk[lane * 8 + t];
        int cum = g;
#pragma unroll
        for (int off = 1; off < 32; off <<= 1) {
            int o = __shfl_up_sync(0xFFFFFFFFu, cum, off);
            if (lane >= off) cum += o;
        }
        unsigned ball = __ballot_sync(0xFFFFFFFFu, cum >= KNB);
        int firstl = __ffs(ball) - 1;
        if (lane == firstl) {
            int c = cum - g;   // exclusive cum before this lane's 8 chunks
            int T = -1;
            for (int t = 0; t < 8 && T < 0; t++) {
                int ch = lane * 8 + t;
                int cs = s_chunk[ch];
                if (c + cs >= KNB) {
                    for (int bd = 0; bd < 8; bd++) {
                        int bin = ch * 8 + bd;
                        int hv = s_hist[bin];
                        if (c + hv >= KNB) { T = bin; break; }
                        c += hv;
                    }
                } else c += cs;
            }
            s_T = T;
        }
    }
    __syncthreads();
    const int Tbin = s_T;

    // ---- Step 3: compaction (clamped writes) ----
#pragma unroll
    for (int u = 0; u < 8; u++) {
        int j = u * 256 + tid;
        unsigned bits = __float_as_uint(d2v[u]);
        int key = (int)(bits >> 20);
        if (key < Tbin) {
            int pos = atomicAdd(&s_na, 1);
            if (pos < KNB)
                s_sel[pos] = ((unsigned long long)bits << 32) | (unsigned)j;
        } else if (key == Tbin) {
            int pos = atomicAdd(&s_nb, 1);
            if (pos < BND_MAX)
                s_bnd[pos] = ((unsigned long long)bits << 32) | (unsigned)j;
        }
    }
    __syncthreads();

    // ---- Step 4: pick the remaining (32 - na) smallest from boundary bin ----
    if (warp == 0) {
        const int na = min(s_na, KNB);
        const int nb = min(s_nb, BND_MAX);
        const int krem = KNB - na;
        for (int r = 0; r < krem; r++) {
            unsigned long long m = U64MAX;
            for (int t = lane; t < nb; t += 32) m = min(m, s_bnd[t]);
#pragma unroll
            for (int off = 16; off; off >>= 1) {
                unsigned long long o = __shfl_xor_sync(0xFFFFFFFFu, m, off);
                m = min(m, o);
            }
            for (int t = lane; t < nb; t += 32)
                if (s_bnd[t] == m) s_bnd[t] = U64MAX;
            if (lane == 0) s_sel[na + r] = m;
            __syncwarp();
        }
    }
    __syncthreads();

    if (tid < KNB) {
        unsigned long long k = s_sel[tid];
        s_idx[tid]  = (int)(k & 0xFFFFFFFFu);
        s_dist[tid] = sqrtf(__uint_as_float((unsigned)(k >> 32)));
    }
    __syncthreads();

    // rotary cos/sin: freqs[m] = min(dist*100,5000) * 10000^(-2m/64)
    {
        const int m = tid & 31;
        const float invf = exp2f((float)m * -0.41524099657040455f);
#pragma unroll
        for (int idx = tid; idx < KNB * 32; idx += 256) {
            int r = idx >> 5;
            float t = fminf(s_dist[r] * 100.0f, 5000.0f);
            float s, c;
            __sincosf(t * invf, &s, &c);
            s_cos[r][m] = c;
            s_sin[r][m] = s;
        }
    }
    __syncthreads();

    // q loads deferred to first use (short live range across selection)
    const int hb = warp * DHEAD;
    const long qbase = (long)row * QKVN + hb;
    const float2 qp = *(const float2*)&g_qkv[qbase + 2 * lane];  // q[2l], q[2l+1]
    const float qA = g_qkv[qbase + lane];                        // q[l]
    const float qB = g_qkv[qbase + lane + 32];                   // q[l+32]

    // qk logits: lane l holds k pair (2l, 2l+1); zero rotate-half shuffles.
    const int si1 = lane >> 1;
    const int si2 = 16 + (lane >> 1);
#pragma unroll 4
    for (int r = 0; r < KNB; r++) {
        const long kb = (long)(b * NPTS + s_idx[r]) * QKVN + INNER + hb;
        float2 kv = *(const float2*)&g_qkv[kb + 2 * lane];
        float C  = s_cos[r][lane];
        float S1 = s_sin[r][si1];
        float S2 = s_sin[r][si2];
        float t = fmaf(qp.y, kv.y, qp.x * kv.x);
        float sum = C * t;
        sum = fmaf(S2, qB * kv.x, sum);
        sum = fmaf(-S1, qA * kv.y, sum);
#pragma unroll
        for (int off = 16; off; off >>= 1)
            sum += __shfl_down_sync(0xFFFFFFFFu, sum, off);
        if (lane == 0) s_qk[warp][r] = sum * 0.125f;
    }
    __syncthreads();

    // tiny MLPs, parallel over (neighbor j, head/slot s): tid = j*8 + s
    {
        const int j = tid >> 3;
        const int s = tid & 7;
        float in[HEADS];
#pragma unroll
        for (int h = 0; h < HEADS; h++) in[h] = s_qk[h][j];
#pragma unroll
        for (int t = 0; t < 2; t++) {
            const int m = 2 * s + t;
            float a = bc1[m];
#pragma unroll
            for (int h = 0; h < HEADS; h++) a += in[h] * wc1[h * 16 + m];
            float x3 = a * a * a;
            float tt = tanhf(0.7978845608028654f * (a + 0.044715f * x3));
            s_hid[j][m] = 0.5f * a * (1.0f + tt);
        }
        __syncwarp();
        float a = bc2[s];
#pragma unroll
        for (int m = 0; m < 16; m++) a += s_hid[j][m] * wc2[m * 8 + s];
        s_cw[j][s] = a;
        float gg = bg[s];
#pragma unroll
        for (int h = 0; h < HEADS; h++) gg += in[h] * wg[h * 8 + s];
        s_gate[j][s] = tanhf(gg);
    }
    __syncthreads();

    // softmaxes: warp h handles head h, lane j handles neighbor j
    {
        const int h = warp;
        float v = s_qk[h][lane];
        float mx = v;
#pragma unroll
        for (int off = 16; off; off >>= 1)
            mx = fmaxf(mx, __shfl_xor_sync(0xFFFFFFFFu, mx, off));
        float e = expf(v - mx);
        float ssum = e;
#pragma unroll
        for (int off = 16; off; off >>= 1)
            ssum += __shfl_xor_sync(0xFFFFFFFFu, ssum, off);
        s_attn[h][lane] = e / ssum;

        float w = s_cw[lane][h];
        float mx2 = w;
#pragma unroll
        for (int off = 16; off; off >>= 1)
            mx2 = fmaxf(mx2, __shfl_xor_sync(0xFFFFFFFFu, mx2, off));
        float e2 = expf(w - mx2);
        float ssum2 = e2;
#pragma unroll
        for (int off = 16; off; off >>= 1)
            ssum2 += __shfl_xor_sync(0xFFFFFFFFu, ssum2, off);
        s_cw[lane][h] = e2 / ssum2;
    }
    __syncthreads();

    // coordinates output: warp 0, lane j = neighbor j
    if (warp == 0 && out_coors) {
        float w = 0.f;
#pragma unroll
        for (int h = 0; h < HEADS; h++)
            w += s_cw[lane][h] * s_gate[lane][h] * coors_combine[h];
        const int jj = s_idx[lane];
        const float nrm = fmaxf(s_dist[lane], 1e-8f);
        const float cscale = coors_scale[0] * w / nrm;
        float vx = (cix - cb[jj * 3 + 0]) * cscale;
        float vy = (ciy - cb[jj * 3 + 1]) * cscale;
        float vz = (ciz - cb[jj * 3 + 2]) * cscale;
#pragma unroll
        for (int off = 16; off; off >>= 1) {
            vx += __shfl_xor_sync(0xFFFFFFFFu, vx, off);
            vy += __shfl_xor_sync(0xFFFFFFFFu, vy, off);
            vz += __shfl_xor_sync(0xFFFFFFFFu, vz, off);
        }
        if (lane == 0) {
            out_coors[(long)row * 3 + 0] = vx;
            out_coors[(long)row * 3 + 1] = vy;
            out_coors[(long)row * 3 + 2] = vz;
        }
    }

    // feature output: lane l accumulates dims (2l, 2l+1).
    const int sA = (2 * lane) & 31;
    const int sB = (2 * lane + 1) & 31;
    const bool lo = lane < 16;
    float acc1 = 0.f, acc2 = 0.f;
#pragma unroll 4
    for (int r = 0; r < KNB; r++) {
        const long vb = (long)(b * NPTS + s_idx[r]) * QKVN + 2 * INNER + hb;
        float2 vv = *(const float2*)&g_qkv[vb + 2 * lane];
        float ya = __shfl_sync(0xFFFFFFFFu, vv.y, sA);
        float xa = __shfl_sync(0xFFFFFFFFu, vv.x, sA);
        float yb = __shfl_sync(0xFFFFFFFFu, vv.y, sB);
        float xb = __shfl_sync(0xFFFFFFFFu, vv.x, sB);
        float rot0 = lo ? -ya : xa;
        float rot1 = lo ? -yb : xb;
        float C = s_cos[r][lane];
        float S = s_sin[r][lane];
        float a = s_attn[warp][r];
        float t0 = fmaf(rot0, S, vv.x * C);
        float t1 = fmaf(rot1, S, vv.y * C);
        acc1 = fmaf(a, t0, acc1);
        acc2 = fmaf(a, t1, acc2);
    }
    *(float2*)&g_att[(long)row * INNER + hb + 2 * lane] = make_float2(acc1, acc2);
}

// ---------------------------------------------------------------------------
extern "C" void kernel_launch(void* const* d_in, const int* in_sizes, int n_in,
                              void* d_out, int out_size)
{
    const float* feats         = (const float*)d_in[0];
    const float* coors         = (const float*)d_in[1];
    const float* w_qkv         = (const float*)d_in[2];
    const float* w_out         = (const float*)d_in[3];
    const float* b_out         = (const float*)d_in[4];
    const float* wc1           = (const float*)d_in[5];
    const float* bc1           = (const float*)d_in[6];
    const float* wc2           = (const float*)d_in[7];
    const float* bc2           = (const float*)d_in[8];
    const float* wg            = (const float*)d_in[9];
    const float* bg            = (const float*)d_in[10];
    const float* coors_scale   = (const float*)d_in[11];
    const float* coors_combine = (const float*)d_in[12];

    float* out = (float*)d_out;
    float* out_coors = (out_size >= FEAT_OUT + ROWS * 3) ? out + FEAT_OUT : nullptr;

    float* qkv_ptr = nullptr;
    float* att_ptr = nullptr;
    cudaGetSymbolAddress((void**)&qkv_ptr, g_qkv);
    cudaGetSymbolAddress((void**)&att_ptr, g_att);

    // 1) qkv = feats @ w_qkv  (TF32 tensor cores)
    {
        dim3 grid(QKVN / 128, ROWS / 128);
        tf32_gemm_kernel<<<grid, 256>>>(feats, w_qkv, qkv_ptr, ROWS, QKVN, DIMF, nullptr);
    }
    // 2) fused neighbor selection (histogram top-k) + attention
    sa_kernel<<<ROWS, 256>>>(coors, wc1, bc1, wc2, bc2, wg, bg,
                             coors_scale, coors_combine, out_coors);
    // 3) out = att @ w_out + b_out  (TF32 tensor cores)
    {
        dim3 grid(DIMF / 128, ROWS / 128);
        tf32_gemm_kernel<<<grid, 256>>>(att_ptr, w_out, out, ROWS, DIMF, INNER, b_out);
    }
}

// round 14
// speedup vs baseline: 1.3114x; 1.0507x over previous
#include <cuda_runtime.h>
#include <cuda_bf16.h>
#include <math.h>
#include <stdint.h>

// Problem constants
#define BATCH   2
#define NPTS    2048
#define HEADS   8
#define DHEAD   64
#define KNB     32
#define DIMF    512
#define INNER   512          // HEADS*DHEAD
#define QKVN    1536         // 3*INNER
#define ROWS    (BATCH*NPTS) // 4096
#define FEAT_OUT (ROWS*DIMF) // 2097152

#define U64MAX 0xFFFFFFFFFFFFFFFFULL
#define BND_MAX 256

// Scratch (device globals: allocation-free per harness rules)
__device__ float g_qkv[ROWS * QKVN];   // 25.2 MB
__device__ float g_att[ROWS * INNER];  // 8.4 MB

// ---------------------------------------------------------------------------
// TF32 tensor-core GEMM with register-prefetch double buffering (R11 version).
// ---------------------------------------------------------------------------
__device__ __forceinline__ uint32_t f2tf32(float x) {
    uint32_t r;
    asm("cvt.rna.tf32.f32 %0, %1;" : "=r"(r) : "f"(x));
    return r;
}

__global__ __launch_bounds__(256) void tf32_gemm_kernel(
    const float* __restrict__ A, const float* __restrict__ Bm,
    float* __restrict__ C, int M, int N, int K,
    const float* __restrict__ bias)
{
    constexpr int BM = 128, BN = 128, BK = 32;
    constexpr int AP = BK + 4;   // 36
    constexpr int BP = BN + 8;   // 136
    __shared__ uint32_t As[BM * AP];
    __shared__ uint32_t Bs[BK * BP];

    const int tid = threadIdx.x;
    const int lane = tid & 31;
    const int wid = tid >> 5;
    const int wm = wid & 1;
    const int wn = wid >> 1;
    const int row0 = blockIdx.y * BM;
    const int col0 = blockIdx.x * BN;

    const int g  = lane >> 2;
    const int tg = lane & 3;

    float acc[4][4][4];
#pragma unroll
    for (int i = 0; i < 4; i++)
#pragma unroll
        for (int j = 0; j < 4; j++)
#pragma unroll
            for (int r = 0; r < 4; r++) acc[i][j][r] = 0.f;

    const int ar = tid >> 3;
    const int ac = (tid & 7) * 4;
    const int br = tid >> 5;
    const int bc = (tid & 31) * 4;

    float4 pa[4], pb[4];
#pragma unroll
    for (int p = 0; p < 4; p++) {
        pa[p] = *(const float4*)&A[(long)(row0 + ar + p * 32) * K + ac];
        pb[p] = *(const float4*)&Bm[(long)(br + p * 8) * N + col0 + bc];
    }

    for (int kk = 0; kk < K; kk += BK) {
#pragma unroll
        for (int p = 0; p < 4; p++) {
            uint32_t* as = &As[(ar + p * 32) * AP + ac];
            as[0] = f2tf32(pa[p].x); as[1] = f2tf32(pa[p].y);
            as[2] = f2tf32(pa[p].z); as[3] = f2tf32(pa[p].w);
            uint32_t* bs = &Bs[(br + p * 8) * BP + bc];
            bs[0] = f2tf32(pb[p].x); bs[1] = f2tf32(pb[p].y);
            bs[2] = f2tf32(pb[p].z); bs[3] = f2tf32(pb[p].w);
        }
        __syncthreads();

        if (kk + BK < K) {
#pragma unroll
            for (int p = 0; p < 4; p++) {
                pa[p] = *(const float4*)&A[(long)(row0 + ar + p * 32) * K + kk + BK + ac];
                pb[p] = *(const float4*)&Bm[(long)(kk + BK + br + p * 8) * N + col0 + bc];
            }
        }

#pragma unroll
        for (int ks = 0; ks < 4; ks++) {
            const int k0 = ks * 8;
            uint32_t a[4][4], b[4][2];
#pragma unroll
            for (int mi = 0; mi < 4; mi++) {
                const int r = wm * 64 + mi * 16 + g;
                a[mi][0] = As[r * AP + k0 + tg];
                a[mi][1] = As[(r + 8) * AP + k0 + tg];
                a[mi][2] = As[r * AP + k0 + tg + 4];
                a[mi][3] = As[(r + 8) * AP + k0 + tg + 4];
            }
#pragma unroll
            for (int nj = 0; nj < 4; nj++) {
                const int c = wn * 32 + nj * 8 + g;
                b[nj][0] = Bs[(k0 + tg) * BP + c];
                b[nj][1] = Bs[(k0 + tg + 4) * BP + c];
            }
#pragma unroll
            for (int mi = 0; mi < 4; mi++)
#pragma unroll
                for (int nj = 0; nj < 4; nj++) {
                    asm volatile(
                        "mma.sync.aligned.m16n8k8.row.col.f32.tf32.tf32.f32 "
                        "{%0,%1,%2,%3}, {%4,%5,%6,%7}, {%8,%9}, {%0,%1,%2,%3};"
                        : "+f"(acc[mi][nj][0]), "+f"(acc[mi][nj][1]),
                          "+f"(acc[mi][nj][2]), "+f"(acc[mi][nj][3])
                        : "r"(a[mi][0]), "r"(a[mi][1]), "r"(a[mi][2]), "r"(a[mi][3]),
                          "r"(b[nj][0]), "r"(b[nj][1]));
                }
        }
        __syncthreads();
    }

#pragma unroll
    for (int mi = 0; mi < 4; mi++) {
        const int r = row0 + wm * 64 + mi * 16 + g;
#pragma unroll
        for (int nj = 0; nj < 4; nj++) {
            const int c = col0 + wn * 32 + nj * 8 + 2 * tg;
            float b0 = bias ? bias[c] : 0.f;
            float b1 = bias ? bias[c + 1] : 0.f;
            C[(long)r * N + c]           = acc[mi][nj][0] + b0;
            C[(long)r * N + c + 1]       = acc[mi][nj][1] + b1;
            C[(long)(r + 8) * N + c]     = acc[mi][nj][2] + b0;
            C[(long)(r + 8) * N + c + 1] = acc[mi][nj][3] + b1;
        }
    }
}

// ---------------------------------------------------------------------------
// Fused selection + attention kernel. Histogram top-32 selection; gather
// loops at unroll 8 with precomputed neighbor row offsets in shared.
// ---------------------------------------------------------------------------
__global__ __launch_bounds__(256) void sa_kernel(
    const float* __restrict__ coors,
    const float* __restrict__ wc1, const float* __restrict__ bc1,
    const float* __restrict__ wc2, const float* __restrict__ bc2,
    const float* __restrict__ wg,  const float* __restrict__ bg,
    const float* __restrict__ coors_scale,
    const float* __restrict__ coors_combine,
    float* __restrict__ out_coors)
{
    const int row = blockIdx.x;
    const int b = row >> 11;             // / NPTS
    const int i = row & (NPTS - 1);
    const int tid = threadIdx.x;
    const int lane = tid & 31;
    const int warp = tid >> 5;           // warp == head

    __shared__ int   s_hist[2048];       // 8KB  (bin = d2 bits >> 20)
    __shared__ int   s_chunk[256];       // 1KB
    __shared__ unsigned long long s_bnd[BND_MAX];  // 2KB
    __shared__ unsigned long long s_sel[KNB];
    __shared__ int   s_na, s_nb, s_T;
    __shared__ int   s_idx[KNB];
    __shared__ long  s_off[KNB];         // neighbor row base offsets
    __shared__ float s_dist[KNB];
    __shared__ float s_cos[KNB][32];
    __shared__ float s_sin[KNB][32];
    __shared__ float s_qk[HEADS][KNB];
    __shared__ float s_attn[HEADS][KNB];
    __shared__ float s_cw[KNB][HEADS];
    __shared__ float s_gate[KNB][HEADS];
    __shared__ float s_hid[KNB][16];
    __shared__ float s_ci[3];

    const float* cb = coors + (long)b * NPTS * 3;
    if (tid < 3) s_ci[tid] = cb[i * 3 + tid];
    for (int t = tid; t < 2048; t += 256) s_hist[t] = 0;
    if (tid == 0) { s_na = 0; s_nb = 0; }
    __syncthreads();
    const float cix = s_ci[0], ciy = s_ci[1], ciz = s_ci[2];

    // ---- Selection step 1: d2 + histogram ----
    float d2v[8];
#pragma unroll
    for (int u = 0; u < 8; u++) {
        int j = u * 256 + tid;
        float dx = cix - cb[j * 3 + 0];
        float dy = ciy - cb[j * 3 + 1];
        float dz = ciz - cb[j * 3 + 2];
        float d2 = dx * dx + dy * dy + dz * dz;
        d2v[u] = d2;
        atomicAdd(&s_hist[__float_as_uint(d2) >> 20], 1);
    }
    __syncthreads();

    // ---- Step 2: find threshold bin T (smallest with cum >= 32) ----
    {
        int csum = 0;
#pragma unroll
        for (int t = 0; t < 8; t++) csum += s_hist[tid * 8 + t];
        s_chunk[tid] = csum;
    }
    __syncthreads();
    if (warp == 0) {
        int g = 0;
#pragma unroll
        for (int t = 0; t < 8; t++) g += s_chunk[lane * 8 + t];
        int cum = g;
#pragma unroll
        for (int off = 1; off < 32; off <<= 1) {
            int o = __shfl_up_sync(0xFFFFFFFFu, cum, off);
            if (lane >= off) cum += o;
        }
        unsigned ball = __ballot_sync(0xFFFFFFFFu, cum >= KNB);
        int firstl = __ffs(ball) - 1;
        if (lane == firstl) {
            int c = cum - g;   // exclusive cum before this lane's 8 chunks
            int T = -1;
            for (int t = 0; t < 8 && T < 0; t++) {
                int ch = lane * 8 + t;
                int cs = s_chunk[ch];
                if (c + cs >= KNB) {
                    for (int bd = 0; bd < 8; bd++) {
                        int bin = ch * 8 + bd;
                        int hv = s_hist[bin];
                        if (c + hv >= KNB) { T = bin; break; }
                        c += hv;
                    }
                } else c += cs;
            }
            s_T = T;
        }
    }
    __syncthreads();
    const int Tbin = s_T;

    // ---- Step 3: compaction (clamped writes) ----
#pragma unroll
    for (int u = 0; u < 8; u++) {
        int j = u * 256 + tid;
        unsigned bits = __float_as_uint(d2v[u]);
        int key = (int)(bits >> 20);
        if (key < Tbin) {
            int pos = atomicAdd(&s_na, 1);
            if (pos < KNB)
                s_sel[pos] = ((unsigned long long)bits << 32) | (unsigned)j;
        } else if (key == Tbin) {
            int pos = atomicAdd(&s_nb, 1);
            if (pos < BND_MAX)
                s_bnd[pos] = ((unsigned long long)bits << 32) | (unsigned)j;
        }
    }
    __syncthreads();

    // ---- Step 4: pick the remaining (32 - na) smallest from boundary bin ----
    if (warp == 0) {
        const int na = min(s_na, KNB);
        const int nb = min(s_nb, BND_MAX);
        const int krem = KNB - na;
        for (int r = 0; r < krem; r++) {
            unsigned long long m = U64MAX;
            for (int t = lane; t < nb; t += 32) m = min(m, s_bnd[t]);
#pragma unroll
            for (int off = 16; off; off >>= 1) {
                unsigned long long o = __shfl_xor_sync(0xFFFFFFFFu, m, off);
                m = min(m, o);
            }
            for (int t = lane; t < nb; t += 32)
                if (s_bnd[t] == m) s_bnd[t] = U64MAX;
            if (lane == 0) s_sel[na + r] = m;
            __syncwarp();
        }
    }
    __syncthreads();

    if (tid < KNB) {
        unsigned long long k = s_sel[tid];
        int idx = (int)(k & 0xFFFFFFFFu);
        s_idx[tid]  = idx;
        s_off[tid]  = (long)(b * NPTS + idx) * QKVN;
        s_dist[tid] = sqrtf(__uint_as_float((unsigned)(k >> 32)));
    }
    __syncthreads();

    // rotary cos/sin: freqs[m] = min(dist*100,5000) * 10000^(-2m/64)
    {
        const int m = tid & 31;
        const float invf = exp2f((float)m * -0.41524099657040455f);
#pragma unroll
        for (int idx = tid; idx < KNB * 32; idx += 256) {
            int r = idx >> 5;
            float t = fminf(s_dist[r] * 100.0f, 5000.0f);
            float s, c;
            __sincosf(t * invf, &s, &c);
            s_cos[r][m] = c;
            s_sin[r][m] = s;
        }
    }
    __syncthreads();

    // q loads (deferred to first use)
    const int hb = warp * DHEAD;
    const long qbase = (long)row * QKVN + hb;
    const float2 qp = *(const float2*)&g_qkv[qbase + 2 * lane];  // q[2l], q[2l+1]
    const float qA = g_qkv[qbase + lane];                        // q[l]
    const float qB = g_qkv[qbase + lane + 32];                   // q[l+32]

    // qk logits: lane l holds k pair (2l, 2l+1); zero rotate-half shuffles.
    const int si1 = lane >> 1;
    const int si2 = 16 + (lane >> 1);
#pragma unroll 8
    for (int r = 0; r < KNB; r++) {
        const long kb = s_off[r] + INNER + hb;
        float2 kv = *(const float2*)&g_qkv[kb + 2 * lane];
        float C  = s_cos[r][lane];
        float S1 = s_sin[r][si1];
        float S2 = s_sin[r][si2];
        float t = fmaf(qp.y, kv.y, qp.x * kv.x);
        float sum = C * t;
        sum = fmaf(S2, qB * kv.x, sum);
        sum = fmaf(-S1, qA * kv.y, sum);
#pragma unroll
        for (int off = 16; off; off >>= 1)
            sum += __shfl_down_sync(0xFFFFFFFFu, sum, off);
        if (lane == 0) s_qk[warp][r] = sum * 0.125f;
    }
    __syncthreads();

    // tiny MLPs, parallel over (neighbor j, head/slot s): tid = j*8 + s
    {
        const int j = tid >> 3;
        const int s = tid & 7;
        float in[HEADS];
#pragma unroll
        for (int h = 0; h < HEADS; h++) in[h] = s_qk[h][j];
#pragma unroll
        for (int t = 0; t < 2; t++) {
            const int m = 2 * s + t;
            float a = bc1[m];
#pragma unroll
            for (int h = 0; h < HEADS; h++) a += in[h] * wc1[h * 16 + m];
            float x3 = a * a * a;
            float tt = tanhf(0.7978845608028654f * (a + 0.044715f * x3));
            s_hid[j][m] = 0.5f * a * (1.0f + tt);
        }
        __syncwarp();
        float a = bc2[s];
#pragma unroll
        for (int m = 0; m < 16; m++) a += s_hid[j][m] * wc2[m * 8 + s];
        s_cw[j][s] = a;
        float gg = bg[s];
#pragma unroll
        for (int h = 0; h < HEADS; h++) gg += in[h] * wg[h * 8 + s];
        s_gate[j][s] = tanhf(gg);
    }
    __syncthreads();

    // softmaxes: warp h handles head h, lane j handles neighbor j
    {
        const int h = warp;
        float v = s_qk[h][lane];
        float mx = v;
#pragma unroll
        for (int off = 16; off; off >>= 1)
            mx = fmaxf(mx, __shfl_xor_sync(0xFFFFFFFFu, mx, off));
        float e = expf(v - mx);
        float ssum = e;
#pragma unroll
        for (int off = 16; off; off >>= 1)
            ssum += __shfl_xor_sync(0xFFFFFFFFu, ssum, off);
        s_attn[h][lane] = e / ssum;

        float w = s_cw[lane][h];
        float mx2 = w;
#pragma unroll
        for (int off = 16; off; off >>= 1)
            mx2 = fmaxf(mx2, __shfl_xor_sync(0xFFFFFFFFu, mx2, off));
        float e2 = expf(w - mx2);
        float ssum2 = e2;
#pragma unroll
        for (int off = 16; off; off >>= 1)
            ssum2 += __shfl_xor_sync(0xFFFFFFFFu, ssum2, off);
        s_cw[lane][h] = e2 / ssum2;
    }
    __syncthreads();

    // coordinates output: warp 0, lane j = neighbor j
    if (warp == 0 && out_coors) {
        float w = 0.f;
#pragma unroll
        for (int h = 0; h < HEADS; h++)
            w += s_cw[lane][h] * s_gate[lane][h] * coors_combine[h];
        const int jj = s_idx[lane];
        const float nrm = fmaxf(s_dist[lane], 1e-8f);
        const float cscale = coors_scale[0] * w / nrm;
        float vx = (cix - cb[jj * 3 + 0]) * cscale;
        float vy = (ciy - cb[jj * 3 + 1]) * cscale;
        float vz = (ciz - cb[jj * 3 + 2]) * cscale;
#pragma unroll
        for (int off = 16; off; off >>= 1) {
            vx += __shfl_xor_sync(0xFFFFFFFFu, vx, off);
            vy += __shfl_xor_sync(0xFFFFFFFFu, vy, off);
            vz += __shfl_xor_sync(0xFFFFFFFFu, vz, off);
        }
        if (lane == 0) {
            out_coors[(long)row * 3 + 0] = vx;
            out_coors[(long)row * 3 + 1] = vy;
            out_coors[(long)row * 3 + 2] = vz;
        }
    }

    // feature output: lane l accumulates dims (2l, 2l+1).
    const int sA = (2 * lane) & 31;
    const int sB = (2 * lane + 1) & 31;
    const bool lo = lane < 16;
    float acc1 = 0.f, acc2 = 0.f;
#pragma unroll 8
    for (int r = 0; r < KNB; r++) {
        const long vb = s_off[r] + 2 * INNER + hb;
        float2 vv = *(const float2*)&g_qkv[vb + 2 * lane];
        float ya = __shfl_sync(0xFFFFFFFFu, vv.y, sA);
        float xa = __shfl_sync(0xFFFFFFFFu, vv.x, sA);
        float yb = __shfl_sync(0xFFFFFFFFu, vv.y, sB);
        float xb = __shfl_sync(0xFFFFFFFFu, vv.x, sB);
        float rot0 = lo ? -ya : xa;
        float rot1 = lo ? -yb : xb;
        float C = s_cos[r][lane];
        float S = s_sin[r][lane];
        float a = s_attn[warp][r];
        float t0 = fmaf(rot0, S, vv.x * C);
        float t1 = fmaf(rot1, S, vv.y * C);
        acc1 = fmaf(a, t0, acc1);
        acc2 = fmaf(a, t1, acc2);
    }
    *(float2*)&g_att[(long)row * INNER + hb + 2 * lane] = make_float2(acc1, acc2);
}

// ---------------------------------------------------------------------------
extern "C" void kernel_launch(void* const* d_in, const int* in_sizes, int n_in,
                              void* d_out, int out_size)
{
    const float* feats         = (const float*)d_in[0];
    const float* coors         = (const float*)d_in[1];
    const float* w_qkv         = (const float*)d_in[2];
    const float* w_out         = (const float*)d_in[3];
    const float* b_out         = (const float*)d_in[4];
    const float* wc1           = (const float*)d_in[5];
    const float* bc1           = (const float*)d_in[6];
    const float* wc2           = (const float*)d_in[7];
    const float* bc2           = (const float*)d_in[8];
    const float* wg            = (const float*)d_in[9];
    const float* bg            = (const float*)d_in[10];
    const float* coors_scale   = (const float*)d_in[11];
    const float* coors_combine = (const float*)d_in[12];

    float* out = (float*)d_out;
    float* out_coors = (out_size >= FEAT_OUT + ROWS * 3) ? out + FEAT_OUT : nullptr;

    float* qkv_ptr = nullptr;
    float* att_ptr = nullptr;
    cudaGetSymbolAddress((void**)&qkv_ptr, g_qkv);
    cudaGetSymbolAddress((void**)&att_ptr, g_att);

    // 1) qkv = feats @ w_qkv  (TF32 tensor cores)
    {
        dim3 grid(QKVN / 128, ROWS / 128);
        tf32_gemm_kernel<<<grid, 256>>>(feats, w_qkv, qkv_ptr, ROWS, QKVN, DIMF, nullptr);
    }
    // 2) fused neighbor selection (histogram top-k) + attention
    sa_kernel<<<ROWS, 256>>>(coors, wc1, bc1, wc2, bc2, wg, bg,
                             coors_scale, coors_combine, out_coors);
    // 3) out = att @ w_out + b_out  (TF32 tensor cores)
    {
        dim3 grid(DIMF / 128, ROWS / 128);
        tf32_gemm_kernel<<<grid, 256>>>(att_ptr, w_out, out, ROWS, DIMF, INNER, b_out);
    }
}